// round 4
// baseline (speedup 1.0000x reference)
#include <cuda_runtime.h>
#include <cuda_bf16.h>
#include <cstdint>

// ---------------------------------------------------------------------------
// cosFormer linear attention — pure-bf16 split-precision GEMMs with cp.async
// 3-stage pipelines. All fp32->bf16 hi/lo splitting and trig folding happens
// ONCE in producer kernels; GEMM mainloops are ldmatrix+MMA only.
// ---------------------------------------------------------------------------

#define L_DIM 2048
#define S_DIM 2048
#define B_DIM 4
#define E_DIM 1024
#define D2    (2 * E_DIM)
#define EPS_F 1e-6f
#define PIO2  1.5707963267948966f
#define INV_M (1.0f / 2048.0f)
#define NCHUNK 16
#define NELEM ((size_t)B_DIM * L_DIM * E_DIM)   // 8388608
#define EE    (E_DIM * E_DIM)

typedef __nv_bfloat16 bf16;
typedef __nv_bfloat162 bf162;

// ---------------- scratch (device globals; allocation-free rule) ------------
__device__ bf16 g_Xh[3 * NELEM], g_Xl[3 * NELEM];     // split inputs q,k,v
__device__ bf16 g_Wh[3 * EE],    g_Wl[3 * EE];        // split weights
__device__ bf16 g_QSh[NELEM], g_QSl[NELEM], g_QCh[NELEM], g_QCl[NELEM];
__device__ bf16 g_KSh[NELEM], g_KSl[NELEM], g_KCh[NELEM], g_KCl[NELEM];
__device__ bf16 g_Vh[NELEM],  g_Vl[NELEM];
__device__ bf16 g_KVh[NELEM], g_KVl[NELEM];           // B*D2*E = 8M
__device__ float g_KsumPartS[NCHUNK * B_DIM * E_DIM];
__device__ float g_KsumPartC[NCHUNK * B_DIM * E_DIM];
__device__ float g_KsumS[B_DIM * E_DIM];
__device__ float g_KsumC[B_DIM * E_DIM];
__device__ float g_Z[B_DIM * L_DIM];

// ---------------- asm helpers ----------------------------------------------
__device__ __forceinline__ uint32_t sptr(const void* p) {
    return (uint32_t)__cvta_generic_to_shared(p);
}
__device__ __forceinline__ void cp16(uint32_t dst, const void* src) {
    asm volatile("cp.async.cg.shared.global [%0], [%1], 16;" :: "r"(dst), "l"(src));
}
#define CP_COMMIT asm volatile("cp.async.commit_group;")
#define CP_WAIT1  asm volatile("cp.async.wait_group 1;")

__device__ __forceinline__ void ldm_x4(uint32_t* r, uint32_t a) {
    asm volatile("ldmatrix.sync.aligned.m8n8.x4.shared.b16 {%0,%1,%2,%3}, [%4];"
                 : "=r"(r[0]), "=r"(r[1]), "=r"(r[2]), "=r"(r[3]) : "r"(a));
}
__device__ __forceinline__ void ldm_x4t(uint32_t* r, uint32_t a) {
    asm volatile("ldmatrix.sync.aligned.m8n8.x4.trans.shared.b16 {%0,%1,%2,%3}, [%4];"
                 : "=r"(r[0]), "=r"(r[1]), "=r"(r[2]), "=r"(r[3]) : "r"(a));
}
__device__ __forceinline__ void ldm_x2(uint32_t* r, uint32_t a) {
    asm volatile("ldmatrix.sync.aligned.m8n8.x2.shared.b16 {%0,%1}, [%2];"
                 : "=r"(r[0]), "=r"(r[1]) : "r"(a));
}
__device__ __forceinline__ void ldm_x2t(uint32_t* r, uint32_t a) {
    asm volatile("ldmatrix.sync.aligned.m8n8.x2.trans.shared.b16 {%0,%1}, [%2];"
                 : "=r"(r[0]), "=r"(r[1]) : "r"(a));
}
__device__ __forceinline__ void mma16816(float* c, const uint32_t* a, const uint32_t* b) {
    asm volatile(
        "mma.sync.aligned.m16n8k16.row.col.f32.bf16.bf16.f32 "
        "{%0,%1,%2,%3}, {%4,%5,%6,%7}, {%8,%9}, {%0,%1,%2,%3};"
        : "+f"(c[0]), "+f"(c[1]), "+f"(c[2]), "+f"(c[3])
        : "r"(a[0]), "r"(a[1]), "r"(a[2]), "r"(a[3]), "r"(b[0]), "r"(b[1]));
}
__device__ __forceinline__ void split_bf16(float x, bf16& h, bf16& l) {
    h = __float2bfloat16(x);
    l = __float2bfloat16(x - __bfloat162float(h));
}
__device__ __forceinline__ bf162 split2(float a, float b, bf16* lo) {
    bf16 h0, l0, h1, l1;
    split_bf16(a, h0, l0); split_bf16(b, h1, l1);
    *lo = l0; lo[1] = l1;
    return __halves2bfloat162(h0, h1);
}

#define MMA_BLOCK(AH, BH) \
    _Pragma("unroll") for (int mi = 0; mi < 4; mi++) \
    _Pragma("unroll") for (int ni = 0; ni < 4; ni++) mma16816(cacc[mi][ni], AH[mi], BH[ni]);

// ---------------- split kernel ---------------------------------------------
__global__ void split_kernel(const float4* __restrict__ src,
                             bf162* __restrict__ h, bf162* __restrict__ l, int n4)
{
    int i = blockIdx.x * 256 + threadIdx.x;
    if (i >= n4) return;
    float4 v = src[i];
    bf16 lo[2];
    bf162 hh = split2(v.x, v.y, lo);
    h[i * 2] = hh; l[i * 2] = __halves2bfloat162(lo[0], lo[1]);
    hh = split2(v.z, v.w, lo);
    h[i * 2 + 1] = hh; l[i * 2 + 1] = __halves2bfloat162(lo[0], lo[1]);
}

// ---------------------------------------------------------------------------
// proj: C[m,n] = X[m,:]·W[n,:] + bias; mode 0: relu + trig dual-output (Q/K),
// mode 1: plain (V). Outputs bf16 hi/lo at [b][t][n].
// ---------------------------------------------------------------------------
#define P_STAGE 40960   // bytes per stage: 4 arrays * 5120 elems * 2B
#define P_SMEM  (3 * P_STAGE)
__global__ __launch_bounds__(256) void proj_mma(
    const bf16* __restrict__ Xh, const bf16* __restrict__ Xl,
    const bf16* __restrict__ Wh, const bf16* __restrict__ Wl,
    const float* __restrict__ bias,
    bf16* __restrict__ o0h, bf16* __restrict__ o0l,
    bf16* __restrict__ o1h, bf16* __restrict__ o1l, int mode)
{
    extern __shared__ bf16 sm[];
    const int tid = threadIdx.x, lane = tid & 31, warp = tid >> 5;
    const int wy = warp >> 2, wx = warp & 3;
    const int m0 = blockIdx.y * 128, n0 = blockIdx.x * 128;
    const uint32_t smb = sptr(sm);

    uint32_t aA[4], aB[4];
    {
        int ar = lane & 15, ac = (lane >> 4) << 3;
#pragma unroll
        for (int mi = 0; mi < 4; mi++)
            aA[mi] = smb + ((wy * 64 + mi * 16 + ar) * 40 + ac) * 2;
        int br = lane & 7, bc = ((lane >> 3) & 1) << 3;
#pragma unroll
        for (int ni = 0; ni < 4; ni++)
            aB[ni] = smb + 20480 + ((wx * 32 + ni * 8 + br) * 40 + bc) * 2;
    }

    auto load_stage = [&](int st, int k0) {
        uint32_t base = smb + st * P_STAGE;
#pragma unroll
        for (int u = 0; u < 2; u++) {
            int id = tid + u * 256;
            int row = id >> 2, seg = id & 3;
            uint32_t da = base + (row * 40 + seg * 8) * 2;
            size_t ga = (size_t)(m0 + row) * E_DIM + k0 + seg * 8;
            cp16(da, Xh + ga); cp16(da + 10240, Xl + ga);
            size_t gb = (size_t)(n0 + row) * E_DIM + k0 + seg * 8;
            cp16(da + 20480, Wh + gb); cp16(da + 30720, Wl + gb);
        }
    };

    float cacc[4][4][4];
#pragma unroll
    for (int i = 0; i < 4; i++)
#pragma unroll
        for (int j = 0; j < 4; j++)
#pragma unroll
            for (int k = 0; k < 4; k++) cacc[i][j][k] = 0.f;

    load_stage(0, 0);  CP_COMMIT;
    load_stage(1, 32); CP_COMMIT;
    int buf = 0;
    for (int k0 = 0; k0 < E_DIM; k0 += 32) {
        CP_WAIT1; __syncthreads();
        if (k0 + 64 < E_DIM) {
            int nst = buf + 2; if (nst >= 3) nst -= 3;
            load_stage(nst, k0 + 64);
        }
        CP_COMMIT;
        uint32_t soff = buf * P_STAGE;
#pragma unroll
        for (int kk = 0; kk < 32; kk += 16) {
            uint32_t ko = soff + kk * 2;
            uint32_t ah[4][4], al[4][4], bh[4][2], bl[4][2];
#pragma unroll
            for (int mi = 0; mi < 4; mi++) { ldm_x4(ah[mi], aA[mi] + ko); ldm_x4(al[mi], aA[mi] + ko + 10240); }
#pragma unroll
            for (int ni = 0; ni < 4; ni++) { ldm_x2(bh[ni], aB[ni] + ko); ldm_x2(bl[ni], aB[ni] + ko + 10240); }
            MMA_BLOCK(ah, bh); MMA_BLOCK(ah, bl); MMA_BLOCK(al, bh);
        }
        buf++; if (buf == 3) buf = 0;
    }

    const int gid = lane >> 2, tig = lane & 3;
#pragma unroll
    for (int mi = 0; mi < 4; mi++)
#pragma unroll
        for (int ni = 0; ni < 4; ni++) {
            int col = n0 + wx * 32 + ni * 8 + tig * 2;
            float b0v = bias[col], b1v = bias[col + 1];
#pragma unroll
            for (int half = 0; half < 2; half++) {
                int m = m0 + wy * 64 + mi * 16 + gid + half * 8;
                int bb = m & (B_DIM - 1);
                int t = m >> 2;
                float c0 = cacc[mi][ni][half * 2] + b0v;
                float c1 = cacc[mi][ni][half * 2 + 1] + b1v;
                size_t o = ((size_t)bb * L_DIM + t) * E_DIM + col;
                bf16 lo[2];
                if (mode == 0) {
                    c0 = fmaxf(c0, 0.f); c1 = fmaxf(c1, 0.f);
                    float th = PIO2 * (float)(t + 1) * INV_M;
                    float sn = __sinf(th), cs = __cosf(th);
                    bf162 hh = split2(sn * c0, sn * c1, lo);
                    *(bf162*)&o0h[o] = hh; *(bf162*)&o0l[o] = __halves2bfloat162(lo[0], lo[1]);
                    hh = split2(cs * c0, cs * c1, lo);
                    *(bf162*)&o1h[o] = hh; *(bf162*)&o1l[o] = __halves2bfloat162(lo[0], lo[1]);
                } else {
                    bf162 hh = split2(c0, c1, lo);
                    *(bf162*)&o0h[o] = hh; *(bf162*)&o0l[o] = __halves2bfloat162(lo[0], lo[1]);
                }
            }
        }
}

// ---------------------------------------------------------------------------
// kv: KV[b,d,m] = sum_s ksel[b,s,d] * v[b,s,m]. A [s][d] (trans ldm), B [s][m]
// (trans ldm). Output hi/lo bf16.
// ---------------------------------------------------------------------------
#define K_STAGE 34816   // 4 * 4352 elems * 2B
#define K_SMEM  (3 * K_STAGE)
__global__ __launch_bounds__(256) void kv_mma(
    const bf16* __restrict__ ksh, const bf16* __restrict__ ksl,
    const bf16* __restrict__ kch, const bf16* __restrict__ kcl,
    const bf16* __restrict__ vh,  const bf16* __restrict__ vl,
    bf16* __restrict__ kvh, bf16* __restrict__ kvl)
{
    extern __shared__ bf16 sm[];
    const int tid = threadIdx.x, lane = tid & 31, warp = tid >> 5;
    const int wy = warp >> 2, wx = warp & 3;
    const int b = blockIdx.z, d0 = blockIdx.y * 128, m0 = blockIdx.x * 128;
    const uint32_t smb = sptr(sm);

    const bf16 *Ahg, *Alg;
    int dbase;
    if (d0 < E_DIM) { Ahg = ksh; Alg = ksl; dbase = d0; }
    else            { Ahg = kch; Alg = kcl; dbase = d0 - E_DIM; }
    Ahg += (size_t)b * S_DIM * E_DIM; Alg += (size_t)b * S_DIM * E_DIM;
    const bf16* Vhg = vh + (size_t)b * S_DIM * E_DIM;
    const bf16* Vlg = vl + (size_t)b * S_DIM * E_DIM;

    uint32_t aA[4], aB[4];
    {
        int ar = (lane & 7) + ((lane >> 4) << 3);
        int ac = ((lane >> 3) & 1) << 3;
#pragma unroll
        for (int mi = 0; mi < 4; mi++)
            aA[mi] = smb + (ar * 136 + wy * 64 + mi * 16 + ac) * 2;
        int br = lane & 15;
#pragma unroll
        for (int ni = 0; ni < 4; ni++)
            aB[ni] = smb + 17408 + (br * 136 + wx * 32 + ni * 8) * 2;
    }

    auto load_stage = [&](int st, int s0) {
        uint32_t base = smb + st * K_STAGE;
#pragma unroll
        for (int u = 0; u < 2; u++) {
            int id = tid + u * 256;
            int row = id >> 4, seg = id & 15;
            uint32_t da = base + (row * 136 + seg * 8) * 2;
            size_t ga = (size_t)(s0 + row) * E_DIM + dbase + seg * 8;
            cp16(da, Ahg + ga); cp16(da + 8704, Alg + ga);
            size_t gb = (size_t)(s0 + row) * E_DIM + m0 + seg * 8;
            cp16(da + 17408, Vhg + gb); cp16(da + 26112, Vlg + gb);
        }
    };

    float cacc[4][4][4];
#pragma unroll
    for (int i = 0; i < 4; i++)
#pragma unroll
        for (int j = 0; j < 4; j++)
#pragma unroll
            for (int k = 0; k < 4; k++) cacc[i][j][k] = 0.f;

    load_stage(0, 0);  CP_COMMIT;
    load_stage(1, 32); CP_COMMIT;
    int buf = 0;
    for (int s0 = 0; s0 < S_DIM; s0 += 32) {
        CP_WAIT1; __syncthreads();
        if (s0 + 64 < S_DIM) {
            int nst = buf + 2; if (nst >= 3) nst -= 3;
            load_stage(nst, s0 + 64);
        }
        CP_COMMIT;
        uint32_t soff = buf * K_STAGE;
#pragma unroll
        for (int kk = 0; kk < 32; kk += 16) {
            uint32_t ko = soff + kk * 272;
            uint32_t ah[4][4], al[4][4], bh[4][2], bl[4][2];
#pragma unroll
            for (int mi = 0; mi < 4; mi++) { ldm_x4t(ah[mi], aA[mi] + ko); ldm_x4t(al[mi], aA[mi] + ko + 8704); }
#pragma unroll
            for (int ni = 0; ni < 4; ni++) { ldm_x2t(bh[ni], aB[ni] + ko); ldm_x2t(bl[ni], aB[ni] + ko + 8704); }
            MMA_BLOCK(ah, bh); MMA_BLOCK(ah, bl); MMA_BLOCK(al, bh);
        }
        buf++; if (buf == 3) buf = 0;
    }

    const int gid = lane >> 2, tig = lane & 3;
#pragma unroll
    for (int mi = 0; mi < 4; mi++)
#pragma unroll
        for (int ni = 0; ni < 4; ni++) {
            int col = m0 + wx * 32 + ni * 8 + tig * 2;
#pragma unroll
            for (int half = 0; half < 2; half++) {
                int d = d0 + wy * 64 + mi * 16 + gid + half * 8;
                size_t o = ((size_t)b * D2 + d) * E_DIM + col;
                bf16 lo[2];
                bf162 hh = split2(cacc[mi][ni][half * 2], cacc[mi][ni][half * 2 + 1], lo);
                *(bf162*)&kvh[o] = hh;
                *(bf162*)&kvl[o] = __halves2bfloat162(lo[0], lo[1]);
            }
        }
}

// ---------------------------------------------------------------------------
// attn: out[l,b,m] = Z[b,l] * sum_d qsel[b,l,d] * KV[b,d,m]
// A [l][d] row-major (non-trans), B [d][m] (trans).
// ---------------------------------------------------------------------------
#define A_STAGE 37888   // (2*5120 + 2*4352) elems * 2B
#define A_SMEM  (3 * A_STAGE)
__global__ __launch_bounds__(256) void attn_mma(
    const bf16* __restrict__ qsh, const bf16* __restrict__ qsl,
    const bf16* __restrict__ qch, const bf16* __restrict__ qcl,
    const bf16* __restrict__ kvh, const bf16* __restrict__ kvl,
    float* __restrict__ out)
{
    extern __shared__ bf16 sm[];
    const int tid = threadIdx.x, lane = tid & 31, warp = tid >> 5;
    const int wy = warp >> 2, wx = warp & 3;
    const int b = blockIdx.z, l0 = blockIdx.y * 128, m0 = blockIdx.x * 128;
    const uint32_t smb = sptr(sm);

    const bf16* QSh = qsh + (size_t)b * L_DIM * E_DIM;
    const bf16* QSl = qsl + (size_t)b * L_DIM * E_DIM;
    const bf16* QCh = qch + (size_t)b * L_DIM * E_DIM;
    const bf16* QCl = qcl + (size_t)b * L_DIM * E_DIM;
    const bf16* KVh = kvh + (size_t)b * D2 * E_DIM;
    const bf16* KVl = kvl + (size_t)b * D2 * E_DIM;

    uint32_t aA[4], aB[4];
    {
        int ar = lane & 15, ac = (lane >> 4) << 3;
#pragma unroll
        for (int mi = 0; mi < 4; mi++)
            aA[mi] = smb + ((wy * 64 + mi * 16 + ar) * 40 + ac) * 2;
        int br = lane & 15;
#pragma unroll
        for (int ni = 0; ni < 4; ni++)
            aB[ni] = smb + 20480 + (br * 136 + wx * 32 + ni * 8) * 2;
    }

    auto load_stage = [&](int st, int k0) {
        uint32_t base = smb + st * A_STAGE;
        const bf16* qh; const bf16* ql; int dloc;
        if (k0 < E_DIM) { qh = QSh; ql = QSl; dloc = k0; }
        else            { qh = QCh; ql = QCl; dloc = k0 - E_DIM; }
#pragma unroll
        for (int u = 0; u < 2; u++) {
            int id = tid + u * 256;
            int row = id >> 2, seg = id & 3;
            uint32_t da = base + (row * 40 + seg * 8) * 2;
            size_t ga = (size_t)(l0 + row) * E_DIM + dloc + seg * 8;
            cp16(da, qh + ga); cp16(da + 10240, ql + ga);
            int rowB = id >> 4, segB = id & 15;
            uint32_t db = base + 20480 + (rowB * 136 + segB * 8) * 2;
            size_t gb = (size_t)(k0 + rowB) * E_DIM + m0 + segB * 8;
            cp16(db, KVh + gb); cp16(db + 8704, KVl + gb);
        }
    };

    float cacc[4][4][4];
#pragma unroll
    for (int i = 0; i < 4; i++)
#pragma unroll
        for (int j = 0; j < 4; j++)
#pragma unroll
            for (int k = 0; k < 4; k++) cacc[i][j][k] = 0.f;

    load_stage(0, 0);  CP_COMMIT;
    load_stage(1, 32); CP_COMMIT;
    int buf = 0;
    for (int k0 = 0; k0 < D2; k0 += 32) {
        CP_WAIT1; __syncthreads();
        if (k0 + 64 < D2) {
            int nst = buf + 2; if (nst >= 3) nst -= 3;
            load_stage(nst, k0 + 64);
        }
        CP_COMMIT;
        uint32_t soff = buf * A_STAGE;
#pragma unroll
        for (int kk = 0; kk < 32; kk += 16) {
            uint32_t koA = soff + kk * 2;
            uint32_t koB = soff + kk * 272;
            uint32_t ah[4][4], al[4][4], bh[4][2], bl[4][2];
#pragma unroll
            for (int mi = 0; mi < 4; mi++) { ldm_x4(ah[mi], aA[mi] + koA); ldm_x4(al[mi], aA[mi] + koA + 10240); }
#pragma unroll
            for (int ni = 0; ni < 4; ni++) { ldm_x2t(bh[ni], aB[ni] + koB); ldm_x2t(bl[ni], aB[ni] + koB + 8704); }
            MMA_BLOCK(ah, bh); MMA_BLOCK(ah, bl); MMA_BLOCK(al, bh);
        }
        buf++; if (buf == 3) buf = 0;
    }

    const int gid = lane >> 2, tig = lane & 3;
#pragma unroll
    for (int mi = 0; mi < 4; mi++)
#pragma unroll
        for (int ni = 0; ni < 4; ni++) {
            int col = m0 + wx * 32 + ni * 8 + tig * 2;
#pragma unroll
            for (int half = 0; half < 2; half++) {
                int l = l0 + wy * 64 + mi * 16 + gid + half * 8;
                float zv = g_Z[b * L_DIM + l];
                *(float2*)&out[((size_t)l * B_DIM + b) * E_DIM + col] =
                    make_float2(cacc[mi][ni][half * 2] * zv, cacc[mi][ni][half * 2 + 1] * zv);
            }
        }
}

// ---------------------------------------------------------------------------
// ksum + z (consume trig-folded split arrays)
// ---------------------------------------------------------------------------
__global__ void ksum_part_kernel()
{
    const int f = blockIdx.x * 256 + threadIdx.x;
    const int b = blockIdx.y;
    const int chunk = blockIdx.z;
    const int s0 = chunk * (S_DIM / NCHUNK);
    float ss = 0.f, sc = 0.f;
#pragma unroll 4
    for (int i = 0; i < S_DIM / NCHUNK; i++) {
        size_t idx = ((size_t)b * S_DIM + s0 + i) * E_DIM + f;
        ss += __bfloat162float(g_KSh[idx]) + __bfloat162float(g_KSl[idx]);
        sc += __bfloat162float(g_KCh[idx]) + __bfloat162float(g_KCl[idx]);
    }
    g_KsumPartS[(chunk * B_DIM + b) * E_DIM + f] = ss;
    g_KsumPartC[(chunk * B_DIM + b) * E_DIM + f] = sc;
}

__global__ void ksum_reduce_kernel()
{
    int idx = blockIdx.x * 256 + threadIdx.x;
    if (idx >= B_DIM * E_DIM) return;
    float ss = 0.f, sc = 0.f;
#pragma unroll
    for (int c = 0; c < NCHUNK; c++) {
        ss += g_KsumPartS[c * B_DIM * E_DIM + idx];
        sc += g_KsumPartC[c * B_DIM * E_DIM + idx];
    }
    g_KsumS[idx] = ss;
    g_KsumC[idx] = sc;
}

__global__ void z_kernel()
{
    const int l = blockIdx.x;
    const int b = blockIdx.y;
    const int tid = threadIdx.x;
    const size_t base = ((size_t)b * L_DIM + l) * E_DIM;

    float acc = 0.f;
#pragma unroll
    for (int f = tid; f < E_DIM; f += 256) {
        float qs = __bfloat162float(g_QSh[base + f]) + __bfloat162float(g_QSl[base + f]);
        float qc = __bfloat162float(g_QCh[base + f]) + __bfloat162float(g_QCl[base + f]);
        acc += qs * g_KsumS[b * E_DIM + f] + qc * g_KsumC[b * E_DIM + f];
    }
    __shared__ float red[8];
#pragma unroll
    for (int off = 16; off > 0; off >>= 1)
        acc += __shfl_down_sync(0xFFFFFFFFu, acc, off);
    if ((tid & 31) == 0) red[tid >> 5] = acc;
    __syncthreads();
    if (tid == 0) {
        float s = 0.f;
#pragma unroll
        for (int w = 0; w < 8; w++) s += red[w];
        g_Z[b * L_DIM + l] = 1.f / fmaxf(s, EPS_F);
    }
}

// ---------------------------------------------------------------------------
// Launch
// ---------------------------------------------------------------------------
extern "C" void kernel_launch(void* const* d_in, const int* in_sizes, int n_in,
                              void* d_out, int out_size)
{
    const float* query = (const float*)d_in[0];
    const float* key   = (const float*)d_in[1];
    const float* value = (const float*)d_in[2];
    const float* Wq    = (const float*)d_in[3];
    const float* bq    = (const float*)d_in[4];
    const float* Wk    = (const float*)d_in[5];
    const float* bk    = (const float*)d_in[6];
    const float* Wv    = (const float*)d_in[7];
    const float* bv    = (const float*)d_in[8];
    float* out = (float*)d_out;

    static bool attr_done = false;
    if (!attr_done) {
        cudaFuncSetAttribute(proj_mma, cudaFuncAttributeMaxDynamicSharedMemorySize, P_SMEM);
        cudaFuncSetAttribute(kv_mma,   cudaFuncAttributeMaxDynamicSharedMemorySize, K_SMEM);
        cudaFuncSetAttribute(attn_mma, cudaFuncAttributeMaxDynamicSharedMemorySize, A_SMEM);
        attr_done = true;
    }

    bf16 *Xh, *Xl, *Wh, *Wl;
    bf16 *QSh, *QSl, *QCh, *QCl, *KSh, *KSl, *KCh, *KCl, *Vh, *Vl, *KVh, *KVl;
    cudaGetSymbolAddress((void**)&Xh, g_Xh);   cudaGetSymbolAddress((void**)&Xl, g_Xl);
    cudaGetSymbolAddress((void**)&Wh, g_Wh);   cudaGetSymbolAddress((void**)&Wl, g_Wl);
    cudaGetSymbolAddress((void**)&QSh, g_QSh); cudaGetSymbolAddress((void**)&QSl, g_QSl);
    cudaGetSymbolAddress((void**)&QCh, g_QCh); cudaGetSymbolAddress((void**)&QCl, g_QCl);
    cudaGetSymbolAddress((void**)&KSh, g_KSh); cudaGetSymbolAddress((void**)&KSl, g_KSl);
    cudaGetSymbolAddress((void**)&KCh, g_KCh); cudaGetSymbolAddress((void**)&KCl, g_KCl);
    cudaGetSymbolAddress((void**)&Vh, g_Vh);   cudaGetSymbolAddress((void**)&Vl, g_Vl);
    cudaGetSymbolAddress((void**)&KVh, g_KVh); cudaGetSymbolAddress((void**)&KVl, g_KVl);

    // split inputs + weights
    int n4x = (int)(NELEM / 4);
    split_kernel<<<n4x / 256, 256>>>((const float4*)query, (bf162*)Xh, (bf162*)Xl, n4x);
    split_kernel<<<n4x / 256, 256>>>((const float4*)key,   (bf162*)(Xh + NELEM), (bf162*)(Xl + NELEM), n4x);
    split_kernel<<<n4x / 256, 256>>>((const float4*)value, (bf162*)(Xh + 2 * NELEM), (bf162*)(Xl + 2 * NELEM), n4x);
    int n4w = EE / 4;
    split_kernel<<<n4w / 256, 256>>>((const float4*)Wq, (bf162*)Wh, (bf162*)Wl, n4w);
    split_kernel<<<n4w / 256, 256>>>((const float4*)Wk, (bf162*)(Wh + EE), (bf162*)(Wl + EE), n4w);
    split_kernel<<<n4w / 256, 256>>>((const float4*)Wv, (bf162*)(Wh + 2 * EE), (bf162*)(Wl + 2 * EE), n4w);

    dim3 gProj(E_DIM / 128, (L_DIM * B_DIM) / 128);   // (8, 64)
    proj_mma<<<gProj, 256, P_SMEM>>>(Xh, Xl, Wh, Wl, bq, QSh, QSl, QCh, QCl, 0);
    proj_mma<<<gProj, 256, P_SMEM>>>(Xh + NELEM, Xl + NELEM, Wh + EE, Wl + EE, bk,
                                     KSh, KSl, KCh, KCl, 0);
    proj_mma<<<gProj, 256, P_SMEM>>>(Xh + 2 * NELEM, Xl + 2 * NELEM, Wh + 2 * EE, Wl + 2 * EE, bv,
                                     Vh, Vl, nullptr, nullptr, 1);

    dim3 gKV(E_DIM / 128, D2 / 128, B_DIM);           // (8, 16, 4)
    kv_mma<<<gKV, 256, K_SMEM>>>(KSh, KSl, KCh, KCl, Vh, Vl, KVh, KVl);

    dim3 gKsum(E_DIM / 256, B_DIM, NCHUNK);
    ksum_part_kernel<<<gKsum, 256>>>();
    ksum_reduce_kernel<<<(B_DIM * E_DIM + 255) / 256, 256>>>();
    dim3 gZ(L_DIM, B_DIM);
    z_kernel<<<gZ, 256>>>();

    dim3 gAttn(E_DIM / 128, L_DIM / 128, B_DIM);      // (8, 16, 4)
    attn_mma<<<gAttn, 256, A_SMEM>>>(QSh, QSl, QCh, QCl, KVh, KVl, out);
}